// round 14
// baseline (speedup 1.0000x reference)
#include <cuda_runtime.h>
#include <cuda_bf16.h>
#include <math.h>
#include <stdint.h>

// Problem constants
#define HID 2048
#define NH  16
#define LAT 512
#define RR  32
#define DH  128
#define CC  96
#define BB  2
#define SS  2048
#define MM  (BB*SS)   // 4096

typedef __nv_bfloat16 bf16;

// ---------------- helpers ----------------
__device__ __forceinline__ void mma16816(float* c, const uint32_t* a, const uint32_t* b) {
    asm volatile(
        "mma.sync.aligned.m16n8k16.row.col.f32.bf16.bf16.f32 "
        "{%0,%1,%2,%3}, {%4,%5,%6,%7}, {%8,%9}, {%0,%1,%2,%3};"
        : "+f"(c[0]), "+f"(c[1]), "+f"(c[2]), "+f"(c[3])
        : "r"(a[0]), "r"(a[1]), "r"(a[2]), "r"(a[3]), "r"(b[0]), "r"(b[1]));
}
__device__ __forceinline__ void ldsm_x4(uint32_t* r, uint32_t addr) {
    asm volatile("ldmatrix.sync.aligned.m8n8.x4.shared.b16 {%0,%1,%2,%3}, [%4];"
                 : "=r"(r[0]), "=r"(r[1]), "=r"(r[2]), "=r"(r[3]) : "r"(addr));
}
__device__ __forceinline__ void split_bf16(float x, bf16& h, bf16& l) {
    h = __float2bfloat16_rn(x);
    l = __float2bfloat16_rn(x - __bfloat162float(h));
}
__device__ __forceinline__ uint32_t pack_bf16(float lo, float hi) {
    __nv_bfloat162 t(__float2bfloat16_rn(lo), __float2bfloat16_rn(hi));
    return *(uint32_t*)&t;
}
__device__ __forceinline__ float bf16f(bf16 x) { return __bfloat162float(x); }
__device__ __forceinline__ uint32_t smem_u32(const void* p) {
    uint32_t a;
    asm("{ .reg .u64 t; cvta.to.shared.u64 t, %1; cvt.u32.u64 %0, t; }" : "=r"(a) : "l"(p));
    return a;
}
__device__ __forceinline__ void cp16(void* dst, const void* src) {
    asm volatile("cp.async.cg.shared.global [%0], [%1], 16;"
                 :: "r"(smem_u32(dst)), "l"(src));
}
#define CP_COMMIT() asm volatile("cp.async.commit_group;" ::: "memory")
#define CP_WAIT0()  asm volatile("cp.async.wait_group 0;" ::: "memory")
#define CP_WAIT1()  asm volatile("cp.async.wait_group 1;" ::: "memory")

// -------- scratch --------
__device__ float g_kr [MM*RR];
__device__ float g_rope[SS*16*2];
__device__ bf16 g_xh [MM*HID],  g_xl [MM*HID];
__device__ bf16 g_lath[MM*1024], g_latl[MM*1024];
__device__ bf16 g_qh [MM*HID],  g_ql [MM*HID];
__device__ bf16 g_kh [MM*HID],  g_kl [MM*HID];
__device__ bf16 g_vth[BB*NH*DH*SS], g_vtl[BB*NH*DH*SS];
__device__ bf16 g_cxh[MM*HID],  g_cxl[MM*HID];
__device__ bf16 g_wdh  [1024*HID], g_wdl  [1024*HID];
__device__ bf16 g_wquph[2048*LAT], g_wqupl[2048*LAT];
__device__ bf16 g_wkuh [CC*NH*LAT], g_wkul[CC*NH*LAT];
__device__ bf16 g_wkrh [RR*HID],   g_wkrl [RR*HID];
__device__ bf16 g_wvuh [HID*LAT],  g_wvul [HID*LAT];
__device__ bf16 g_woh  [HID*HID],  g_wol  [HID*HID];

// ==================== split ====================
__global__ void split_kernel(const float* __restrict__ src,
                             bf16* __restrict__ h, bf16* __restrict__ l, int n)
{
    int i = (blockIdx.x * blockDim.x + threadIdx.x) * 4;
    if (i >= n) return;
    float4 v = *(const float4*)(src + i);
    bf16 hx, lx, hy, ly, hz, lz, hw, lw;
    split_bf16(v.x, hx, lx); split_bf16(v.y, hy, ly);
    split_bf16(v.z, hz, lz); split_bf16(v.w, hw, lw);
    *(__nv_bfloat162*)(h + i)     = __nv_bfloat162(hx, hy);
    *(__nv_bfloat162*)(h + i + 2) = __nv_bfloat162(hz, hw);
    *(__nv_bfloat162*)(l + i)     = __nv_bfloat162(lx, ly);
    *(__nv_bfloat162*)(l + i + 2) = __nv_bfloat162(lz, lw);
}

// ==================== bf16-plane GEMM, cp.async + ldmatrix ====================
// EPI 0: fp32 out (ldc) + optional bias
// EPI 1: bf16 planes out (ldc)
// EPI 2: bf16 planes out, V-transposed [b,h,d,s]
// EPI 3: fused q assembly: N=2048 = [qc(1536) | qr(512)], RoPE in registers,
//        writes planes at [t, h*128+d]
// EPI 4: fused k partial assembly: N=1536 = kc, writes planes at [t, h*128+d], d<96
template<int BM, int BN, int WARPS_M, int WARPS_N, int EPI>
__global__ __launch_bounds__(256) void gemm_bf16_kernel(
    const bf16* __restrict__ Ah, const bf16* __restrict__ Al,
    const bf16* __restrict__ Bh, const bf16* __restrict__ Bl,
    const float* __restrict__ bias, const float* __restrict__ tab,
    float* __restrict__ C,
    bf16* __restrict__ Oh, bf16* __restrict__ Ol,
    int M, int N, int K, int lda, int ldc)
{
    constexpr int BK = 32, ST = 40;
    constexpr int WTM = BM / WARPS_M;
    constexpr int WTN = BN / WARPS_N;
    constexpr int MT = WTM / 16;
    constexpr int NT = WTN / 8;
    constexpr int SSZ = (2*BM + 2*BN) * ST;

    extern __shared__ bf16 sm[];

    const int bm = blockIdx.y * BM;
    const int bn = blockIdx.x * BN;
    const int tid = threadIdx.x;
    const int wid = tid >> 5;
    const int lane = tid & 31;
    const int wm = wid / WARPS_N;
    const int wn = wid % WARPS_N;
    const int g = lane >> 2;
    const int tig = lane & 3;
    const int lrowA = (lane & 7) + ((lane >> 3) & 1) * 8;
    const int lcolA = (lane >> 4) * 8;
    const int mtx   = lane >> 3;
    const int lrowB = (mtx >> 1) * 8 + (lane & 7);
    const int lcolB = (mtx & 1) * 8;

    const uint32_t sm_u = smem_u32(sm);

    float acc[MT][NT][4];
#pragma unroll
    for (int mt = 0; mt < MT; mt++)
#pragma unroll
        for (int nt = 0; nt < NT; nt++)
#pragma unroll
            for (int i = 0; i < 4; i++) acc[mt][nt][i] = 0.f;

    const int nc = K / BK;

    auto load_stage = [&](int chunk, int s) {
        const long k0 = (long)chunk * BK;
        bf16* stg = sm + s * SSZ;
#pragma unroll
        for (int it = 0; it < (BM*4 + 255) / 256; it++) {
            int f = tid + it * 256;
            if (f < BM*4) {
                int row = f >> 2, cg = f & 3;
                long goff = (long)(bm + row) * lda + k0 + cg * 8;
                cp16(stg + row*ST + cg*8, Ah + goff);
                cp16(stg + BM*ST + row*ST + cg*8, Al + goff);
            }
        }
#pragma unroll
        for (int it = 0; it < (BN*4 + 255) / 256; it++) {
            int f = tid + it * 256;
            if (f < BN*4) {
                int row = f >> 2, cg = f & 3;
                long goff = (long)(bn + row) * K + k0 + cg * 8;
                cp16(stg + 2*BM*ST + row*ST + cg*8, Bh + goff);
                cp16(stg + 2*BM*ST + BN*ST + row*ST + cg*8, Bl + goff);
            }
        }
    };

    load_stage(0, 0);
    CP_COMMIT();

    for (int c = 0; c < nc; c++) {
        const int buf = c & 1;
        if (c + 1 < nc) {
            load_stage(c + 1, buf ^ 1);
            CP_COMMIT();
            CP_WAIT1();
        } else {
            CP_WAIT0();
        }
        __syncthreads();

        const uint32_t uAh = sm_u + (buf * SSZ) * 2;
        const uint32_t uAl = uAh + BM*ST*2;
        const uint32_t uBh = uAh + 2*BM*ST*2;
        const uint32_t uBl = uBh + BN*ST*2;

#pragma unroll
        for (int kk = 0; kk < BK; kk += 16) {
            uint32_t afh[MT][4], afl[MT][4], bfh[NT][2], bfl[NT][2];
#pragma unroll
            for (int mt = 0; mt < MT; mt++) {
                int off = ((wm*WTM + mt*16 + lrowA) * ST + kk + lcolA) * 2;
                ldsm_x4(afh[mt], uAh + off);
                ldsm_x4(afl[mt], uAl + off);
            }
#pragma unroll
            for (int np = 0; np < NT/2; np++) {
                int off = ((wn*WTN + np*16 + lrowB) * ST + kk + lcolB) * 2;
                uint32_t r[4];
                ldsm_x4(r, uBh + off);
                bfh[2*np][0]=r[0]; bfh[2*np][1]=r[1]; bfh[2*np+1][0]=r[2]; bfh[2*np+1][1]=r[3];
                ldsm_x4(r, uBl + off);
                bfl[2*np][0]=r[0]; bfl[2*np][1]=r[1]; bfl[2*np+1][0]=r[2]; bfl[2*np+1][1]=r[3];
            }
#pragma unroll
            for (int mt = 0; mt < MT; mt++)
#pragma unroll
                for (int nt = 0; nt < NT; nt++) {
                    mma16816(acc[mt][nt], afh[mt], bfh[nt]);
                    mma16816(acc[mt][nt], afh[mt], bfl[nt]);
                    mma16816(acc[mt][nt], afl[mt], bfh[nt]);
                }
        }
        __syncthreads();
    }

    // ---- epilogue ----
    const bool qr_tile = (EPI == 3) && (bn + wn * WTN >= 1536);  // whole warp tile in qr
#pragma unroll
    for (int mt = 0; mt < MT; mt++) {
        int row0 = bm + wm * WTM + mt * 16 + g;
        int s0 = row0 & (SS - 1), s8 = (row0 + 8) & (SS - 1);
#pragma unroll
        for (int nt = 0; nt < NT; nt++) {
            int colb = bn + wn * WTN + nt * 8 + tig * 2;
            if (EPI == 0) {
                float b0 = bias ? bias[colb] : 0.f;
                float b1 = bias ? bias[colb + 1] : 0.f;
                *(float2*)&C[(long)row0 * ldc + colb] =
                    make_float2(acc[mt][nt][0] + b0, acc[mt][nt][1] + b1);
                *(float2*)&C[(long)(row0 + 8) * ldc + colb] =
                    make_float2(acc[mt][nt][2] + b0, acc[mt][nt][3] + b1);
            } else if (EPI == 1) {
                long i0 = (long)row0 * ldc + colb;
                long i1 = (long)(row0 + 8) * ldc + colb;
                bf16 h, l;
                split_bf16(acc[mt][nt][0], h, l); Oh[i0]   = h; Ol[i0]   = l;
                split_bf16(acc[mt][nt][1], h, l); Oh[i0+1] = h; Ol[i0+1] = l;
                split_bf16(acc[mt][nt][2], h, l); Oh[i1]   = h; Ol[i1]   = l;
                split_bf16(acc[mt][nt][3], h, l); Oh[i1+1] = h; Ol[i1+1] = l;
            } else if (EPI == 2) {
                int s = row0 & (SS - 1);
                int bb = row0 >> 11;
                long i0 = ((long)(bb * NH + (colb >> 7)) * DH + (colb & 127)) * SS + s;
                bf16 h, l;
                split_bf16(acc[mt][nt][0], h, l); Oh[i0]      = h; Ol[i0]      = l;
                split_bf16(acc[mt][nt][1], h, l); Oh[i0+SS]   = h; Ol[i0+SS]   = l;
                split_bf16(acc[mt][nt][2], h, l); Oh[i0+8]    = h; Ol[i0+8]    = l;
                split_bf16(acc[mt][nt][3], h, l); Oh[i0+SS+8] = h; Ol[i0+SS+8] = l;
            } else if (EPI == 3) {
                if (!qr_tile) {
                    // qc: col -> (h=col/96, d=col%96)
#pragma unroll
                    for (int j = 0; j < 2; j++) {
                        int col = colb + j;
                        int hh = col / 96, d = col - hh * 96;
                        long o0 = (long)row0 * HID + hh * 128 + d;
                        long o8 = (long)(row0 + 8) * HID + hh * 128 + d;
                        bf16 bh_, bl_;
                        split_bf16(acc[mt][nt][j],   bh_, bl_); Oh[o0] = bh_; Ol[o0] = bl_;
                        split_bf16(acc[mt][nt][2+j], bh_, bl_); Oh[o8] = bh_; Ol[o8] = bl_;
                    }
                } else {
                    // qr: c = col-1536; h=c>>5, r=c&31; partner at nt^2 (16 cols away)
                    int c = colb - 1536;
                    int hq = c >> 5, r = c & 31;
                    float sgn = (r < 16) ? -1.f : 1.f;
#pragma unroll
                    for (int j = 0; j < 2; j++) {
                        int rr = r + j;
                        int i = rr & 15;
                        float cs0 = tab[(s0*16+i)*2+0], sn0 = tab[(s0*16+i)*2+1];
                        float cs8 = tab[(s8*16+i)*2+0], sn8 = tab[(s8*16+i)*2+1];
                        float x0 = acc[mt][nt][j],   p0 = acc[mt][nt ^ 2][j];
                        float x8 = acc[mt][nt][2+j], p8 = acc[mt][nt ^ 2][2+j];
                        float v0 = x0 * cs0 + sgn * p0 * sn0;
                        float v8 = x8 * cs8 + sgn * p8 * sn8;
                        long o0 = (long)row0 * HID + hq * 128 + 96 + rr;
                        long o8 = (long)(row0 + 8) * HID + hq * 128 + 96 + rr;
                        bf16 bh_, bl_;
                        split_bf16(v0, bh_, bl_); Oh[o0] = bh_; Ol[o0] = bl_;
                        split_bf16(v8, bh_, bl_); Oh[o8] = bh_; Ol[o8] = bl_;
                    }
                }
            } else {  // EPI == 4: k partial (d<96)
#pragma unroll
                for (int j = 0; j < 2; j++) {
                    int col = colb + j;
                    int hh = col / 96, d = col - hh * 96;
                    long o0 = (long)row0 * HID + hh * 128 + d;
                    long o8 = (long)(row0 + 8) * HID + hh * 128 + d;
                    bf16 bh_, bl_;
                    split_bf16(acc[mt][nt][j],   bh_, bl_); Oh[o0] = bh_; Ol[o0] = bl_;
                    split_bf16(acc[mt][nt][2+j], bh_, bl_); Oh[o8] = bh_; Ol[o8] = bl_;
                }
            }
        }
    }
}

// ==================== RoPE table ====================
__global__ void rope_table_kernel(float* __restrict__ tab)
{
    int idx = blockIdx.x * blockDim.x + threadIdx.x;
    if (idx >= SS * 16) return;
    int i = idx & 15;
    int s = idx >> 4;
    float inv = powf(10000.0f, -(float)i / 16.0f);
    float freq = (float)s * inv;
    float cs, sn;
    sincosf(freq, &sn, &cs);
    tab[idx*2+0] = cs;
    tab[idx*2+1] = sn;
}

// ==================== k rope tail: kr -> kh/kl planes (d>=96, all heads) ====================
__global__ void assemble_kr_kernel(const float* __restrict__ kr,
                                   const float* __restrict__ tab,
                                   bf16* __restrict__ kh, bf16* __restrict__ kl)
{
    int idx = blockIdx.x * blockDim.x + threadIdx.x;   // t*32 + r
    if (idx >= MM * RR) return;
    int r = idx & 31, t = idx >> 5;
    int s = t & (SS - 1);
    int i = r & 15;
    float cs = tab[(s*16+i)*2+0], sn = tab[(s*16+i)*2+1];
    const float* base = kr + (long)t * RR;
    float x = base[r];
    float xr = (r < 16) ? -base[r + 16] : base[r - 16];
    float val = x * cs + xr * sn;
    bf16 hh, ll;
    split_bf16(val, hh, ll);
    long o = (long)t * HID + 96 + r;
#pragma unroll
    for (int h = 0; h < NH; h++) { kh[o + h*128] = hh; kl[o + h*128] = ll; }
}

// ==================== Flash attention (64 q-rows/CTA, round-10 form) ====================
#define QST 136
#define VST 72

__global__ __launch_bounds__(128) void flash_mma_kernel(
    const bf16* __restrict__ Qh_, const bf16* __restrict__ Ql_,
    const bf16* __restrict__ Kh_, const bf16* __restrict__ Kl_,
    const bf16* __restrict__ Vth_, const bf16* __restrict__ Vtl_,
    bf16* __restrict__ Oh, bf16* __restrict__ Ol)
{
    extern __shared__ bf16 smf[];
    bf16* sQh = smf;
    bf16* sQl = sQh + 64*QST;
    bf16* sKh = sQl + 64*QST;
    bf16* sKl = sKh + 64*QST;
    bf16* sVh = sKl + 64*QST;
    bf16* sVl = sVh + 128*VST;

    const int qb = blockIdx.x;
    const int h  = blockIdx.y;
    const int b  = blockIdx.z;
    const int tid = threadIdx.x;
    const int w = tid >> 5;
    const int lane = tid & 31;
    const int g = lane >> 2;
    const int tig = lane & 3;
    const int RS = NH * DH;
    const float scale = 0.08838834764831845f;
    const int lrowA = (lane & 7) + ((lane >> 3) & 1) * 8;
    const int lcolA = (lane >> 4) * 8;
    const int mtx   = lane >> 3;
    const int lrowB = (mtx >> 1) * 8 + (lane & 7);
    const int lcolB = (mtx & 1) * 8;

    const uint32_t uQh = smem_u32(sQh), uQl = smem_u32(sQl);
    const uint32_t uKh = smem_u32(sKh), uKl = smem_u32(sKl);
    const uint32_t uVh = smem_u32(sVh), uVl = smem_u32(sVl);

    {
        const long qoff = ((long)b * SS + qb * 64) * RS + h * DH;
#pragma unroll
        for (int it = 0; it < 8; it++) {
            int f = tid + it * 128;
            int row = f >> 4, ch = (f & 15) * 8;
            cp16(sQh + row*QST + ch, Qh_ + qoff + (long)row * RS + ch);
            cp16(sQl + row*QST + ch, Ql_ + qoff + (long)row * RS + ch);
        }
        CP_COMMIT();
    }

    float m0 = -1e30f, m8 = -1e30f, l0 = 0.f, l8 = 0.f;
    float o[16][4];
#pragma unroll
    for (int nd = 0; nd < 16; nd++)
#pragma unroll
        for (int i = 0; i < 4; i++) o[nd][i] = 0.f;

    for (int kb = 0; kb <= qb; kb++) {
        __syncthreads();
        {
            const long koff = ((long)b * SS + kb * 64) * RS + h * DH;
#pragma unroll
            for (int it = 0; it < 8; it++) {
                int f = tid + it * 128;
                int row = f >> 4, ch = (f & 15) * 8;
                cp16(sKh + row*QST + ch, Kh_ + koff + (long)row * RS + ch);
                cp16(sKl + row*QST + ch, Kl_ + koff + (long)row * RS + ch);
            }
            const long voff = (long)(b * NH + h) * DH * SS + kb * 64;
#pragma unroll
            for (int it = 0; it < 8; it++) {
                int f = tid + it * 128;
                int row = f >> 3, ch = (f & 7) * 8;
                cp16(sVh + row*VST + ch, Vth_ + voff + (long)row * SS + ch);
                cp16(sVl + row*VST + ch, Vtl_ + voff + (long)row * SS + ch);
            }
            CP_COMMIT();
            CP_WAIT0();
        }
        __syncthreads();

        float sc[8][4];
#pragma unroll
        for (int nt = 0; nt < 8; nt++)
#pragma unroll
            for (int i = 0; i < 4; i++) sc[nt][i] = 0.f;

#pragma unroll
        for (int kk = 0; kk < 128; kk += 16) {
            uint32_t ah[4], al[4];
            {
                int off = ((w*16 + lrowA) * QST + kk + lcolA) * 2;
                ldsm_x4(ah, uQh + off);
                ldsm_x4(al, uQl + off);
            }
            uint32_t bh[8][2], bl[8][2];
#pragma unroll
            for (int np = 0; np < 4; np++) {
                int off = ((np*16 + lrowB) * QST + kk + lcolB) * 2;
                uint32_t r[4];
                ldsm_x4(r, uKh + off);
                bh[2*np][0]=r[0]; bh[2*np][1]=r[1]; bh[2*np+1][0]=r[2]; bh[2*np+1][1]=r[3];
                ldsm_x4(r, uKl + off);
                bl[2*np][0]=r[0]; bl[2*np][1]=r[1]; bl[2*np+1][0]=r[2]; bl[2*np+1][1]=r[3];
            }
#pragma unroll
            for (int nt = 0; nt < 8; nt++) {
                mma16816(sc[nt], ah, bh[nt]);
                mma16816(sc[nt], ah, bl[nt]);
                mma16816(sc[nt], al, bh[nt]);
            }
        }

#pragma unroll
        for (int nt = 0; nt < 8; nt++)
#pragma unroll
            for (int i = 0; i < 4; i++) sc[nt][i] *= scale;
        if (kb == qb) {
            int row0 = qb*64 + w*16 + g;
#pragma unroll
            for (int nt = 0; nt < 8; nt++) {
                int col = kb*64 + nt*8 + tig*2;
                if (col     > row0)     sc[nt][0] = -1e30f;
                if (col + 1 > row0)     sc[nt][1] = -1e30f;
                if (col     > row0 + 8) sc[nt][2] = -1e30f;
                if (col + 1 > row0 + 8) sc[nt][3] = -1e30f;
            }
        }

        float r0 = -1e30f, r8 = -1e30f;
#pragma unroll
        for (int nt = 0; nt < 8; nt++) {
            r0 = fmaxf(r0, fmaxf(sc[nt][0], sc[nt][1]));
            r8 = fmaxf(r8, fmaxf(sc[nt][2], sc[nt][3]));
        }
        r0 = fmaxf(r0, __shfl_xor_sync(0xffffffffu, r0, 1));
        r0 = fmaxf(r0, __shfl_xor_sync(0xffffffffu, r0, 2));
        r8 = fmaxf(r8, __shfl_xor_sync(0xffffffffu, r8, 1));
        r8 = fmaxf(r8, __shfl_xor_sync(0xffffffffu, r8, 2));
        float mn0 = fmaxf(m0, r0), mn8 = fmaxf(m8, r8);
        float alpha0 = __expf(m0 - mn0), alpha8 = __expf(m8 - mn8);
        float s0 = 0.f, s8 = 0.f;
#pragma unroll
        for (int nt = 0; nt < 8; nt++) {
            sc[nt][0] = __expf(sc[nt][0] - mn0);
            sc[nt][1] = __expf(sc[nt][1] - mn0);
            sc[nt][2] = __expf(sc[nt][2] - mn8);
            sc[nt][3] = __expf(sc[nt][3] - mn8);
            s0 += sc[nt][0] + sc[nt][1];
            s8 += sc[nt][2] + sc[nt][3];
        }
        s0 += __shfl_xor_sync(0xffffffffu, s0, 1);
        s0 += __shfl_xor_sync(0xffffffffu, s0, 2);
        s8 += __shfl_xor_sync(0xffffffffu, s8, 1);
        s8 += __shfl_xor_sync(0xffffffffu, s8, 2);
        l0 = l0 * alpha0 + s0; l8 = l8 * alpha8 + s8;
        m0 = mn0; m8 = mn8;
#pragma unroll
        for (int nd = 0; nd < 16; nd++) {
            o[nd][0] *= alpha0; o[nd][1] *= alpha0;
            o[nd][2] *= alpha8; o[nd][3] *= alpha8;
        }

#pragma unroll
        for (int t = 0; t < 4; t++) {
            uint32_t ph[4], pl[4];
            {
                float p00 = sc[2*t][0],   p01 = sc[2*t][1];
                float p02 = sc[2*t][2],   p03 = sc[2*t][3];
                float p10 = sc[2*t+1][0], p11 = sc[2*t+1][1];
                float p12 = sc[2*t+1][2], p13 = sc[2*t+1][3];
                ph[0] = pack_bf16(p00, p01);
                ph[1] = pack_bf16(p02, p03);
                ph[2] = pack_bf16(p10, p11);
                ph[3] = pack_bf16(p12, p13);
                __nv_bfloat162 hh;
                hh = *(__nv_bfloat162*)&ph[0];
                pl[0] = pack_bf16(p00 - bf16f(hh.x), p01 - bf16f(hh.y));
                hh = *(__nv_bfloat162*)&ph[1];
                pl[1] = pack_bf16(p02 - bf16f(hh.x), p03 - bf16f(hh.y));
                hh = *(__nv_bfloat162*)&ph[2];
                pl[2] = pack_bf16(p10 - bf16f(hh.x), p11 - bf16f(hh.y));
                hh = *(__nv_bfloat162*)&ph[3];
                pl[3] = pack_bf16(p12 - bf16f(hh.x), p13 - bf16f(hh.y));
            }
#pragma unroll
            for (int np = 0; np < 8; np++) {
                int off = ((np*16 + lrowB) * VST + t*16 + lcolB) * 2;
                uint32_t vh[4], vl[4];
                ldsm_x4(vh, uVh + off);
                ldsm_x4(vl, uVl + off);
                mma16816(o[2*np],   ph, vh);
                mma16816(o[2*np],   ph, vl);
                mma16816(o[2*np],   pl, vh);
                mma16816(o[2*np+1], ph, vh + 2);
                mma16816(o[2*np+1], ph, vl + 2);
                mma16816(o[2*np+1], pl, vh + 2);
            }
        }
    }

    {
        float inv0 = 1.0f / l0, inv8 = 1.0f / l8;
        int row0 = qb*64 + w*16 + g;
        long i0 = ((long)b * SS + row0) * RS + h * DH;
        long i8 = i0 + 8L * RS;
#pragma unroll
        for (int nd = 0; nd < 16; nd++) {
            int col = nd*8 + tig*2;
            float v0 = o[nd][0] * inv0, v1 = o[nd][1] * inv0;
            float v2 = o[nd][2] * inv8, v3 = o[nd][3] * inv8;
            bf16 hh, ll;
            split_bf16(v0, hh, ll); Oh[i0 + col]     = hh; Ol[i0 + col]     = ll;
            split_bf16(v1, hh, ll); Oh[i0 + col + 1] = hh; Ol[i0 + col + 1] = ll;
            split_bf16(v2, hh, ll); Oh[i8 + col]     = hh; Ol[i8 + col]     = ll;
            split_bf16(v3, hh, ll); Oh[i8 + col + 1] = hh; Ol[i8 + col + 1] = ll;
        }
    }
}

// ==================== launchers ====================
static inline void launch_split(const float* s, bf16* h, bf16* l, int n) {
    split_kernel<<<(n/4 + 255)/256, 256>>>(s, h, l, n);
}

template<int EPI>
static void run_gemm(const bf16* Ah, const bf16* Al, const bf16* Bh, const bf16* Bl,
                     const float* bias, const float* tab, float* C, bf16* Oh, bf16* Ol,
                     int M, int N, int K, int lda, int ldc)
{
    if (N % 128 == 0) {
        constexpr int SMEM = 2 * (2*128 + 2*128) * 40 * 2;
        cudaFuncSetAttribute(gemm_bf16_kernel<128,128,4,2,EPI>,
                             cudaFuncAttributeMaxDynamicSharedMemorySize, SMEM);
        dim3 grid(N / 128, M / 128);
        gemm_bf16_kernel<128,128,4,2,EPI><<<grid, 256, SMEM>>>(
            Ah, Al, Bh, Bl, bias, tab, C, Oh, Ol, M, N, K, lda, ldc);
    } else {
        constexpr int SMEM = 2 * (2*64 + 2*32) * 40 * 2;
        cudaFuncSetAttribute(gemm_bf16_kernel<64,32,4,2,EPI>,
                             cudaFuncAttributeMaxDynamicSharedMemorySize, SMEM);
        dim3 grid(N / 32, M / 64);
        gemm_bf16_kernel<64,32,4,2,EPI><<<grid, 256, SMEM>>>(
            Ah, Al, Bh, Bl, bias, tab, C, Oh, Ol, M, N, K, lda, ldc);
    }
}

#define SYM(p, s) cudaGetSymbolAddress((void**)&p, s)

extern "C" void kernel_launch(void* const* d_in, const int* in_sizes, int n_in,
                              void* d_out, int out_size)
{
    const float* x       = (const float*)d_in[0];
    const float* Wq_down = (const float*)d_in[1];
    const float* Wq_up   = (const float*)d_in[2];
    const float* Wq_rope = (const float*)d_in[3];
    const float* Wkv_down= (const float*)d_in[4];
    const float* Wk_up   = (const float*)d_in[5];
    const float* Wk_rope = (const float*)d_in[6];
    const float* Wv_up   = (const float*)d_in[7];
    const float* Wo      = (const float*)d_in[8];
    const float* bo      = (const float*)d_in[9];
    float* out = (float*)d_out;

    float *kr, *tab;
    SYM(kr, g_kr); SYM(tab, g_rope);
    bf16 *xh,*xl,*lath,*latl,*qh,*ql,*kh,*kl,*vth,*vtl,*cxh,*cxl;
    SYM(xh, g_xh); SYM(xl, g_xl); SYM(lath, g_lath); SYM(latl, g_latl);
    SYM(qh, g_qh); SYM(ql, g_ql); SYM(kh, g_kh); SYM(kl, g_kl);
    SYM(vth, g_vth); SYM(vtl, g_vtl); SYM(cxh, g_cxh); SYM(cxl, g_cxl);
    bf16 *wdh,*wdl,*wquph,*wqupl,*wkuh,*wkul,*wkrh,*wkrl,*wvuh,*wvul,*woh,*wol;
    SYM(wdh, g_wdh); SYM(wdl, g_wdl); SYM(wquph, g_wquph); SYM(wqupl, g_wqupl);
    SYM(wkuh, g_wkuh); SYM(wkul, g_wkul); SYM(wkrh, g_wkrh); SYM(wkrl, g_wkrl);
    SYM(wvuh, g_wvuh); SYM(wvul, g_wvul); SYM(woh, g_woh); SYM(wol, g_wol);

    // position #4 = big fused down-GEMM (ncu -s 5 lands there)
    launch_split(x,        xh, xl, MM*HID);                                   // 1
    launch_split(Wq_down,  wdh,           wdl,           LAT*HID);            // 2
    launch_split(Wkv_down, wdh + LAT*HID, wdl + LAT*HID, LAT*HID);            // 3
    run_gemm<1>(xh, xl, wdh, wdl, nullptr, nullptr, nullptr, lath, latl,
                MM, 1024, HID, HID, 1024);                                     // 4

    rope_table_kernel<<<(SS*16 + 255)/256, 256>>>(tab);
    launch_split(Wk_rope,  wkrh, wkrl, RR*HID);
    launch_split(Wq_up,    wquph,             wqupl,             CC*NH*LAT);
    launch_split(Wq_rope,  wquph + CC*NH*LAT, wqupl + CC*NH*LAT, RR*NH*LAT);
    launch_split(Wk_up,    wkuh, wkul, CC*NH*LAT);
    launch_split(Wv_up,    wvuh, wvul, HID*LAT);
    launch_split(Wo,       woh,  wol,  HID*HID);

    // kr projection (fp32)
    run_gemm<0>(xh, xl, wkrh, wkrl, nullptr, nullptr, kr, nullptr, nullptr,
                MM, RR, HID, HID, RR);
    // fused q-up + RoPE + assembly -> qh/ql directly
    run_gemm<3>(lath, latl, wquph, wqupl, nullptr, tab, nullptr, qh, ql,
                MM, 2048, LAT, 1024, 0);
    // k-up -> kh/kl (d<96 part) directly
    run_gemm<4>(lath + 512, latl + 512, wkuh, wkul, nullptr, nullptr, nullptr, kh, kl,
                MM, CC*NH, LAT, 1024, 0);
    // v-up -> V transposed planes
    run_gemm<2>(lath + 512, latl + 512, wvuh, wvul, nullptr, nullptr, nullptr, vth, vtl,
                MM, HID, LAT, 1024, 0);
    // k rope tail (d>=96, broadcast to heads)
    assemble_kr_kernel<<<(MM*RR + 255)/256, 256>>>(kr, tab, kh, kl);

    // flash attention -> ctx bf16 planes
    {
        size_t smem = (size_t)(4*64*QST + 2*128*VST) * sizeof(bf16);
        cudaFuncSetAttribute(flash_mma_kernel,
                             cudaFuncAttributeMaxDynamicSharedMemorySize, (int)smem);
        dim3 grid(SS / 64, NH, BB);
        flash_mma_kernel<<<grid, 128, smem>>>(qh, ql, kh, kl, vth, vtl, cxh, cxl);
    }

    // output projection + bias
    run_gemm<0>(cxh, cxl, woh, wol, bo, nullptr, out, nullptr, nullptr,
                MM, HID, HID, HID, HID);
}

// round 15
// speedup vs baseline: 1.6030x; 1.6030x over previous
#include <cuda_runtime.h>
#include <cuda_bf16.h>
#include <math.h>
#include <stdint.h>

// Problem constants
#define HID 2048
#define NH  16
#define LAT 512
#define RR  32
#define DH  128
#define CC  96
#define BB  2
#define SS  2048
#define MM  (BB*SS)   // 4096

typedef __nv_bfloat16 bf16;

// ---------------- helpers ----------------
__device__ __forceinline__ void mma16816(float* c, const uint32_t* a, const uint32_t* b) {
    asm volatile(
        "mma.sync.aligned.m16n8k16.row.col.f32.bf16.bf16.f32 "
        "{%0,%1,%2,%3}, {%4,%5,%6,%7}, {%8,%9}, {%0,%1,%2,%3};"
        : "+f"(c[0]), "+f"(c[1]), "+f"(c[2]), "+f"(c[3])
        : "r"(a[0]), "r"(a[1]), "r"(a[2]), "r"(a[3]), "r"(b[0]), "r"(b[1]));
}
__device__ __forceinline__ void ldsm_x4(uint32_t* r, uint32_t addr) {
    asm volatile("ldmatrix.sync.aligned.m8n8.x4.shared.b16 {%0,%1,%2,%3}, [%4];"
                 : "=r"(r[0]), "=r"(r[1]), "=r"(r[2]), "=r"(r[3]) : "r"(addr));
}
__device__ __forceinline__ void split_bf16(float x, bf16& h, bf16& l) {
    h = __float2bfloat16_rn(x);
    l = __float2bfloat16_rn(x - __bfloat162float(h));
}
// packed: split two floats, store hi pair + lo pair as 4-byte stores
__device__ __forceinline__ void store_planes2(bf16* Oh, bf16* Ol, long i, float a, float b) {
    bf16 h0, l0, h1, l1;
    split_bf16(a, h0, l0); split_bf16(b, h1, l1);
    *(__nv_bfloat162*)(Oh + i) = __nv_bfloat162(h0, h1);
    *(__nv_bfloat162*)(Ol + i) = __nv_bfloat162(l0, l1);
}
__device__ __forceinline__ uint32_t pack_bf16(float lo, float hi) {
    __nv_bfloat162 t(__float2bfloat16_rn(lo), __float2bfloat16_rn(hi));
    return *(uint32_t*)&t;
}
__device__ __forceinline__ float bf16f(bf16 x) { return __bfloat162float(x); }
__device__ __forceinline__ uint32_t smem_u32(const void* p) {
    uint32_t a;
    asm("{ .reg .u64 t; cvta.to.shared.u64 t, %1; cvt.u32.u64 %0, t; }" : "=r"(a) : "l"(p));
    return a;
}
__device__ __forceinline__ void cp16(void* dst, const void* src) {
    asm volatile("cp.async.cg.shared.global [%0], [%1], 16;"
                 :: "r"(smem_u32(dst)), "l"(src));
}
#define CP_COMMIT() asm volatile("cp.async.commit_group;" ::: "memory")
#define CP_WAIT0()  asm volatile("cp.async.wait_group 0;" ::: "memory")
#define CP_WAIT1()  asm volatile("cp.async.wait_group 1;" ::: "memory")

// -------- scratch --------
__device__ float g_qcqr[MM*2048];
__device__ float g_kc [MM*(CC*NH)];
__device__ float g_kr [MM*RR];
__device__ float g_rope[SS*16*2];
__device__ bf16 g_xh [MM*HID],  g_xl [MM*HID];
__device__ bf16 g_lath[MM*1024], g_latl[MM*1024];
__device__ bf16 g_qh [MM*HID],  g_ql [MM*HID];
__device__ bf16 g_kh [MM*HID],  g_kl [MM*HID];
__device__ bf16 g_vth[BB*NH*DH*SS], g_vtl[BB*NH*DH*SS];
__device__ bf16 g_cxh[MM*HID],  g_cxl[MM*HID];
__device__ bf16 g_wdh  [1024*HID], g_wdl  [1024*HID];
__device__ bf16 g_wquph[2048*LAT], g_wqupl[2048*LAT];
__device__ bf16 g_wkuh [CC*NH*LAT], g_wkul[CC*NH*LAT];
__device__ bf16 g_wkrh [RR*HID],   g_wkrl [RR*HID];
__device__ bf16 g_wvuh [HID*LAT],  g_wvul [HID*LAT];
__device__ bf16 g_woh  [HID*HID],  g_wol  [HID*HID];

// ==================== splits ====================
__global__ void split_kernel(const float* __restrict__ src,
                             bf16* __restrict__ h, bf16* __restrict__ l, int n)
{
    int i = (blockIdx.x * blockDim.x + threadIdx.x) * 4;
    if (i >= n) return;
    float4 v = *(const float4*)(src + i);
    bf16 hx, lx, hy, ly, hz, lz, hw, lw;
    split_bf16(v.x, hx, lx); split_bf16(v.y, hy, ly);
    split_bf16(v.z, hz, lz); split_bf16(v.w, hw, lw);
    *(__nv_bfloat162*)(h + i)     = __nv_bfloat162(hx, hy);
    *(__nv_bfloat162*)(h + i + 2) = __nv_bfloat162(hz, hw);
    *(__nv_bfloat162*)(l + i)     = __nv_bfloat162(lx, ly);
    *(__nv_bfloat162*)(l + i + 2) = __nv_bfloat162(lz, lw);
}

// all 8 weight tensors in one launch (segment table by value)
#define NSEG 8
struct WJobs {
    const float* src[NSEG];
    bf16* oh[NSEG];
    bf16* ol[NSEG];
    long cum[NSEG + 1];
};
__global__ void split_w_kernel(WJobs jb)
{
    long i = ((long)blockIdx.x * blockDim.x + threadIdx.x) * 4;
    if (i >= jb.cum[NSEG]) return;
    int s = 0;
#pragma unroll
    for (int k = 0; k < NSEG - 1; k++) s += (i >= jb.cum[k + 1]) ? 1 : 0;
    long off = i - jb.cum[s];
    float4 v = *(const float4*)(jb.src[s] + off);
    bf16 hx, lx, hy, ly, hz, lz, hw, lw;
    split_bf16(v.x, hx, lx); split_bf16(v.y, hy, ly);
    split_bf16(v.z, hz, lz); split_bf16(v.w, hw, lw);
    *(__nv_bfloat162*)(jb.oh[s] + off)     = __nv_bfloat162(hx, hy);
    *(__nv_bfloat162*)(jb.oh[s] + off + 2) = __nv_bfloat162(hz, hw);
    *(__nv_bfloat162*)(jb.ol[s] + off)     = __nv_bfloat162(lx, ly);
    *(__nv_bfloat162*)(jb.ol[s] + off + 2) = __nv_bfloat162(lz, lw);
}

// ==================== bf16-plane GEMM, cp.async + ldmatrix ====================
// EPI 0: fp32 out (ldc) + optional bias
// EPI 1: bf16 planes out (ldc), packed stores
// EPI 2: bf16 planes out, V-transposed [b,h,d,s]
template<int BM, int BN, int WARPS_M, int WARPS_N, int EPI>
__global__ __launch_bounds__(256) void gemm_bf16_kernel(
    const bf16* __restrict__ Ah, const bf16* __restrict__ Al,
    const bf16* __restrict__ Bh, const bf16* __restrict__ Bl,
    const float* __restrict__ bias, float* __restrict__ C,
    bf16* __restrict__ Oh, bf16* __restrict__ Ol,
    int M, int N, int K, int lda, int ldc)
{
    constexpr int BK = 32, ST = 40;
    constexpr int WTM = BM / WARPS_M;
    constexpr int WTN = BN / WARPS_N;
    constexpr int MT = WTM / 16;
    constexpr int NT = WTN / 8;
    constexpr int SSZ = (2*BM + 2*BN) * ST;

    extern __shared__ bf16 sm[];

    const int bm = blockIdx.y * BM;
    const int bn = blockIdx.x * BN;
    const int tid = threadIdx.x;
    const int wid = tid >> 5;
    const int lane = tid & 31;
    const int wm = wid / WARPS_N;
    const int wn = wid % WARPS_N;
    const int g = lane >> 2;
    const int tig = lane & 3;
    const int lrowA = (lane & 7) + ((lane >> 3) & 1) * 8;
    const int lcolA = (lane >> 4) * 8;
    const int mtx   = lane >> 3;
    const int lrowB = (mtx >> 1) * 8 + (lane & 7);
    const int lcolB = (mtx & 1) * 8;

    const uint32_t sm_u = smem_u32(sm);

    float acc[MT][NT][4];
#pragma unroll
    for (int mt = 0; mt < MT; mt++)
#pragma unroll
        for (int nt = 0; nt < NT; nt++)
#pragma unroll
            for (int i = 0; i < 4; i++) acc[mt][nt][i] = 0.f;

    const int nc = K / BK;

    auto load_stage = [&](int chunk, int s) {
        const long k0 = (long)chunk * BK;
        bf16* stg = sm + s * SSZ;
#pragma unroll
        for (int it = 0; it < (BM*4 + 255) / 256; it++) {
            int f = tid + it * 256;
            if (f < BM*4) {
                int row = f >> 2, cg = f & 3;
                long goff = (long)(bm + row) * lda + k0 + cg * 8;
                cp16(stg + row*ST + cg*8, Ah + goff);
                cp16(stg + BM*ST + row*ST + cg*8, Al + goff);
            }
        }
#pragma unroll
        for (int it = 0; it < (BN*4 + 255) / 256; it++) {
            int f = tid + it * 256;
            if (f < BN*4) {
                int row = f >> 2, cg = f & 3;
                long goff = (long)(bn + row) * K + k0 + cg * 8;
                cp16(stg + 2*BM*ST + row*ST + cg*8, Bh + goff);
                cp16(stg + 2*BM*ST + BN*ST + row*ST + cg*8, Bl + goff);
            }
        }
    };

    load_stage(0, 0);
    CP_COMMIT();

    for (int c = 0; c < nc; c++) {
        const int buf = c & 1;
        if (c + 1 < nc) {
            load_stage(c + 1, buf ^ 1);
            CP_COMMIT();
            CP_WAIT1();
        } else {
            CP_WAIT0();
        }
        __syncthreads();

        const uint32_t uAh = sm_u + (buf * SSZ) * 2;
        const uint32_t uAl = uAh + BM*ST*2;
        const uint32_t uBh = uAh + 2*BM*ST*2;
        const uint32_t uBl = uBh + BN*ST*2;

#pragma unroll
        for (int kk = 0; kk < BK; kk += 16) {
            uint32_t afh[MT][4], afl[MT][4], bfh[NT][2], bfl[NT][2];
#pragma unroll
            for (int mt = 0; mt < MT; mt++) {
                int off = ((wm*WTM + mt*16 + lrowA) * ST + kk + lcolA) * 2;
                ldsm_x4(afh[mt], uAh + off);
                ldsm_x4(afl[mt], uAl + off);
            }
#pragma unroll
            for (int np = 0; np < NT/2; np++) {
                int off = ((wn*WTN + np*16 + lrowB) * ST + kk + lcolB) * 2;
                uint32_t r[4];
                ldsm_x4(r, uBh + off);
                bfh[2*np][0]=r[0]; bfh[2*np][1]=r[1]; bfh[2*np+1][0]=r[2]; bfh[2*np+1][1]=r[3];
                ldsm_x4(r, uBl + off);
                bfl[2*np][0]=r[0]; bfl[2*np][1]=r[1]; bfl[2*np+1][0]=r[2]; bfl[2*np+1][1]=r[3];
            }
#pragma unroll
            for (int mt = 0; mt < MT; mt++)
#pragma unroll
                for (int nt = 0; nt < NT; nt++) {
                    mma16816(acc[mt][nt], afh[mt], bfh[nt]);
                    mma16816(acc[mt][nt], afh[mt], bfl[nt]);
                    mma16816(acc[mt][nt], afl[mt], bfh[nt]);
                }
        }
        __syncthreads();
    }

#pragma unroll
    for (int mt = 0; mt < MT; mt++) {
        int row0 = bm + wm * WTM + mt * 16 + g;
#pragma unroll
        for (int nt = 0; nt < NT; nt++) {
            int colb = bn + wn * WTN + nt * 8 + tig * 2;
            if (EPI == 0) {
                float b0 = bias ? bias[colb] : 0.f;
                float b1 = bias ? bias[colb + 1] : 0.f;
                *(float2*)&C[(long)row0 * ldc + colb] =
                    make_float2(acc[mt][nt][0] + b0, acc[mt][nt][1] + b1);
                *(float2*)&C[(long)(row0 + 8) * ldc + colb] =
                    make_float2(acc[mt][nt][2] + b0, acc[mt][nt][3] + b1);
            } else if (EPI == 1) {
                store_planes2(Oh, Ol, (long)row0 * ldc + colb,
                              acc[mt][nt][0], acc[mt][nt][1]);
                store_planes2(Oh, Ol, (long)(row0 + 8) * ldc + colb,
                              acc[mt][nt][2], acc[mt][nt][3]);
            } else {
                int s = row0 & (SS - 1);
                int bb = row0 >> 11;
                long i0 = ((long)(bb * NH + (colb >> 7)) * DH + (colb & 127)) * SS + s;
                bf16 h, l;
                split_bf16(acc[mt][nt][0], h, l); Oh[i0]      = h; Ol[i0]      = l;
                split_bf16(acc[mt][nt][1], h, l); Oh[i0+SS]   = h; Ol[i0+SS]   = l;
                split_bf16(acc[mt][nt][2], h, l); Oh[i0+8]    = h; Ol[i0+8]    = l;
                split_bf16(acc[mt][nt][3], h, l); Oh[i0+SS+8] = h; Ol[i0+SS+8] = l;
            }
        }
    }
}

// ==================== RoPE table ====================
__global__ void rope_table_kernel(float* __restrict__ tab)
{
    int idx = blockIdx.x * blockDim.x + threadIdx.x;
    if (idx >= SS * 16) return;
    int i = idx & 15;
    int s = idx >> 4;
    float inv = powf(10000.0f, -(float)i / 16.0f);
    float freq = (float)s * inv;
    float cs, sn;
    sincosf(freq, &sn, &cs);
    tab[idx*2+0] = cs;
    tab[idx*2+1] = sn;
}

// ==================== head assembly + RoPE -> bf16 planes (2 elems/thread) ====================
__global__ void assemble_q_kernel(const float* __restrict__ qcqr,
                                  const float* __restrict__ tab,
                                  bf16* __restrict__ qh, bf16* __restrict__ ql)
{
    int p = blockIdx.x * blockDim.x + threadIdx.x;
    if (p >= MM*HID/2) return;
    int idx = p * 2;
    int d = idx & 127;           // even; pairs never straddle region boundaries
    int h = (idx >> 7) & 15;
    int t = idx >> 11;
    int s = t & (SS - 1);
    float v0, v1;
    if (d < CC) {
        const float* src = qcqr + (long)t * 2048 + h*CC + d;
        v0 = src[0]; v1 = src[1];
    } else {
        const float* base = qcqr + (long)t * 2048 + 1536 + h*RR;
        int r = d - CC;
#pragma unroll
        for (int j = 0; j < 2; j++) {
            int rr = r + j;
            int i = rr & 15;
            float cs = tab[(s*16+i)*2+0], sn = tab[(s*16+i)*2+1];
            float x = base[rr];
            float xr = (rr < 16) ? -base[rr + 16] : base[rr - 16];
            float v = x * cs + xr * sn;
            if (j == 0) v0 = v; else v1 = v;
        }
    }
    store_planes2(qh, ql, idx, v0, v1);
}

__global__ void assemble_k_kernel(const float* __restrict__ kc,
                                  const float* __restrict__ kr,
                                  const float* __restrict__ tab,
                                  bf16* __restrict__ kh, bf16* __restrict__ kl)
{
    int p = blockIdx.x * blockDim.x + threadIdx.x;
    if (p >= MM*HID/2) return;
    int idx = p * 2;
    int d = idx & 127;
    int h = (idx >> 7) & 15;
    int t = idx >> 11;
    int s = t & (SS - 1);
    float v0, v1;
    if (d < CC) {
        const float* src = kc + (long)t * (CC*NH) + h*CC + d;
        v0 = src[0]; v1 = src[1];
    } else {
        const float* base = kr + (long)t * RR;
        int r = d - CC;
#pragma unroll
        for (int j = 0; j < 2; j++) {
            int rr = r + j;
            int i = rr & 15;
            float cs = tab[(s*16+i)*2+0], sn = tab[(s*16+i)*2+1];
            float x = base[rr];
            float xr = (rr < 16) ? -base[rr + 16] : base[rr - 16];
            float v = x * cs + xr * sn;
            if (j == 0) v0 = v; else v1 = v;
        }
    }
    store_planes2(kh, kl, idx, v0, v1);
}

// ==================== Flash attention (64 q-rows/CTA, round-10 form) ====================
#define QST 136
#define VST 72

__global__ __launch_bounds__(128) void flash_mma_kernel(
    const bf16* __restrict__ Qh_, const bf16* __restrict__ Ql_,
    const bf16* __restrict__ Kh_, const bf16* __restrict__ Kl_,
    const bf16* __restrict__ Vth_, const bf16* __restrict__ Vtl_,
    bf16* __restrict__ Oh, bf16* __restrict__ Ol)
{
    extern __shared__ bf16 smf[];
    bf16* sQh = smf;
    bf16* sQl = sQh + 64*QST;
    bf16* sKh = sQl + 64*QST;
    bf16* sKl = sKh + 64*QST;
    bf16* sVh = sKl + 64*QST;
    bf16* sVl = sVh + 128*VST;

    const int qb = blockIdx.x;
    const int h  = blockIdx.y;
    const int b  = blockIdx.z;
    const int tid = threadIdx.x;
    const int w = tid >> 5;
    const int lane = tid & 31;
    const int g = lane >> 2;
    const int tig = lane & 3;
    const int RS = NH * DH;
    const float scale = 0.08838834764831845f;
    const int lrowA = (lane & 7) + ((lane >> 3) & 1) * 8;
    const int lcolA = (lane >> 4) * 8;
    const int mtx   = lane >> 3;
    const int lrowB = (mtx >> 1) * 8 + (lane & 7);
    const int lcolB = (mtx & 1) * 8;

    const uint32_t uQh = smem_u32(sQh), uQl = smem_u32(sQl);
    const uint32_t uKh = smem_u32(sKh), uKl = smem_u32(sKl);
    const uint32_t uVh = smem_u32(sVh), uVl = smem_u32(sVl);

    {
        const long qoff = ((long)b * SS + qb * 64) * RS + h * DH;
#pragma unroll
        for (int it = 0; it < 8; it++) {
            int f = tid + it * 128;
            int row = f >> 4, ch = (f & 15) * 8;
            cp16(sQh + row*QST + ch, Qh_ + qoff + (long)row * RS + ch);
            cp16(sQl + row*QST + ch, Ql_ + qoff + (long)row * RS + ch);
        }
        CP_COMMIT();
    }

    float m0 = -1e30f, m8 = -1e30f, l0 = 0.f, l8 = 0.f;
    float o[16][4];
#pragma unroll
    for (int nd = 0; nd < 16; nd++)
#pragma unroll
        for (int i = 0; i < 4; i++) o[nd][i] = 0.f;

    for (int kb = 0; kb <= qb; kb++) {
        __syncthreads();
        {
            const long koff = ((long)b * SS + kb * 64) * RS + h * DH;
#pragma unroll
            for (int it = 0; it < 8; it++) {
                int f = tid + it * 128;
                int row = f >> 4, ch = (f & 15) * 8;
                cp16(sKh + row*QST + ch, Kh_ + koff + (long)row * RS + ch);
                cp16(sKl + row*QST + ch, Kl_ + koff + (long)row * RS + ch);
            }
            const long voff = (long)(b * NH + h) * DH * SS + kb * 64;
#pragma unroll
            for (int it = 0; it < 8; it++) {
                int f = tid + it * 128;
                int row = f >> 3, ch = (f & 7) * 8;
                cp16(sVh + row*VST + ch, Vth_ + voff + (long)row * SS + ch);
                cp16(sVl + row*VST + ch, Vtl_ + voff + (long)row * SS + ch);
            }
            CP_COMMIT();
            CP_WAIT0();
        }
        __syncthreads();

        float sc[8][4];
#pragma unroll
        for (int nt = 0; nt < 8; nt++)
#pragma unroll
            for (int i = 0; i < 4; i++) sc[nt][i] = 0.f;

#pragma unroll
        for (int kk = 0; kk < 128; kk += 16) {
            uint32_t ah[4], al[4];
            {
                int off = ((w*16 + lrowA) * QST + kk + lcolA) * 2;
                ldsm_x4(ah, uQh + off);
                ldsm_x4(al, uQl + off);
            }
            uint32_t bh[8][2], bl[8][2];
#pragma unroll
            for (int np = 0; np < 4; np++) {
                int off = ((np*16 + lrowB) * QST + kk + lcolB) * 2;
                uint32_t r[4];
                ldsm_x4(r, uKh + off);
                bh[2*np][0]=r[0]; bh[2*np][1]=r[1]; bh[2*np+1][0]=r[2]; bh[2*np+1][1]=r[3];
                ldsm_x4(r, uKl + off);
                bl[2*np][0]=r[0]; bl[2*np][1]=r[1]; bl[2*np+1][0]=r[2]; bl[2*np+1][1]=r[3];
            }
#pragma unroll
            for (int nt = 0; nt < 8; nt++) {
                mma16816(sc[nt], ah, bh[nt]);
                mma16816(sc[nt], ah, bl[nt]);
                mma16816(sc[nt], al, bh[nt]);
            }
        }

#pragma unroll
        for (int nt = 0; nt < 8; nt++)
#pragma unroll
            for (int i = 0; i < 4; i++) sc[nt][i] *= scale;
        if (kb == qb) {
            int row0 = qb*64 + w*16 + g;
#pragma unroll
            for (int nt = 0; nt < 8; nt++) {
                int col = kb*64 + nt*8 + tig*2;
                if (col     > row0)     sc[nt][0] = -1e30f;
                if (col + 1 > row0)     sc[nt][1] = -1e30f;
                if (col     > row0 + 8) sc[nt][2] = -1e30f;
                if (col + 1 > row0 + 8) sc[nt][3] = -1e30f;
            }
        }

        float r0 = -1e30f, r8 = -1e30f;
#pragma unroll
        for (int nt = 0; nt < 8; nt++) {
            r0 = fmaxf(r0, fmaxf(sc[nt][0], sc[nt][1]));
            r8 = fmaxf(r8, fmaxf(sc[nt][2], sc[nt][3]));
        }
        r0 = fmaxf(r0, __shfl_xor_sync(0xffffffffu, r0, 1));
        r0 = fmaxf(r0, __shfl_xor_sync(0xffffffffu, r0, 2));
        r8 = fmaxf(r8, __shfl_xor_sync(0xffffffffu, r8, 1));
        r8 = fmaxf(r8, __shfl_xor_sync(0xffffffffu, r8, 2));
        float mn0 = fmaxf(m0, r0), mn8 = fmaxf(m8, r8);
        float alpha0 = __expf(m0 - mn0), alpha8 = __expf(m8 - mn8);
        float s0 = 0.f, s8 = 0.f;
#pragma unroll
        for (int nt = 0; nt < 8; nt++) {
            sc[nt][0] = __expf(sc[nt][0] - mn0);
            sc[nt][1] = __expf(sc[nt][1] - mn0);
            sc[nt][2] = __expf(sc[nt][2] - mn8);
            sc[nt][3] = __expf(sc[nt][3] - mn8);
            s0 += sc[nt][0] + sc[nt][1];
            s8 += sc[nt][2] + sc[nt][3];
        }
        s0 += __shfl_xor_sync(0xffffffffu, s0, 1);
        s0 += __shfl_xor_sync(0xffffffffu, s0, 2);
        s8 += __shfl_xor_sync(0xffffffffu, s8, 1);
        s8 += __shfl_xor_sync(0xffffffffu, s8, 2);
        l0 = l0 * alpha0 + s0; l8 = l8 * alpha8 + s8;
        m0 = mn0; m8 = mn8;
#pragma unroll
        for (int nd = 0; nd < 16; nd++) {
            o[nd][0] *= alpha0; o[nd][1] *= alpha0;
            o[nd][2] *= alpha8; o[nd][3] *= alpha8;
        }

#pragma unroll
        for (int t = 0; t < 4; t++) {
            uint32_t ph[4], pl[4];
            {
                float p00 = sc[2*t][0],   p01 = sc[2*t][1];
                float p02 = sc[2*t][2],   p03 = sc[2*t][3];
                float p10 = sc[2*t+1][0], p11 = sc[2*t+1][1];
                float p12 = sc[2*t+1][2], p13 = sc[2*t+1][3];
                ph[0] = pack_bf16(p00, p01);
                ph[1] = pack_bf16(p02, p03);
                ph[2] = pack_bf16(p10, p11);
                ph[3] = pack_bf16(p12, p13);
                __nv_bfloat162 hh;
                hh = *(__nv_bfloat162*)&ph[0];
                pl[0] = pack_bf16(p00 - bf16f(hh.x), p01 - bf16f(hh.y));
                hh = *(__nv_bfloat162*)&ph[1];
                pl[1] = pack_bf16(p02 - bf16f(hh.x), p03 - bf16f(hh.y));
                hh = *(__nv_bfloat162*)&ph[2];
                pl[2] = pack_bf16(p10 - bf16f(hh.x), p11 - bf16f(hh.y));
                hh = *(__nv_bfloat162*)&ph[3];
                pl[3] = pack_bf16(p12 - bf16f(hh.x), p13 - bf16f(hh.y));
            }
#pragma unroll
            for (int np = 0; np < 8; np++) {
                int off = ((np*16 + lrowB) * VST + t*16 + lcolB) * 2;
                uint32_t vh[4], vl[4];
                ldsm_x4(vh, uVh + off);
                ldsm_x4(vl, uVl + off);
                mma16816(o[2*np],   ph, vh);
                mma16816(o[2*np],   ph, vl);
                mma16816(o[2*np],   pl, vh);
                mma16816(o[2*np+1], ph, vh + 2);
                mma16816(o[2*np+1], ph, vl + 2);
                mma16816(o[2*np+1], pl, vh + 2);
            }
        }
    }

    // ---- write ctx bf16 planes (packed stores) ----
    {
        float inv0 = 1.0f / l0, inv8 = 1.0f / l8;
        int row0 = qb*64 + w*16 + g;
        long i0 = ((long)b * SS + row0) * RS + h * DH;
        long i8 = i0 + 8L * RS;
#pragma unroll
        for (int nd = 0; nd < 16; nd++) {
            int col = nd*8 + tig*2;
            store_planes2(Oh, Ol, i0 + col, o[nd][0] * inv0, o[nd][1] * inv0);
            store_planes2(Oh, Ol, i8 + col, o[nd][2] * inv8, o[nd][3] * inv8);
        }
    }
}

// ==================== launchers ====================
template<int EPI>
static void run_gemm(const bf16* Ah, const bf16* Al, const bf16* Bh, const bf16* Bl,
                     const float* bias, float* C, bf16* Oh, bf16* Ol,
                     int M, int N, int K, int lda, int ldc)
{
    if (N % 128 == 0) {
        constexpr int SMEM = 2 * (2*128 + 2*128) * 40 * 2;
        cudaFuncSetAttribute(gemm_bf16_kernel<128,128,4,2,EPI>,
                             cudaFuncAttributeMaxDynamicSharedMemorySize, SMEM);
        dim3 grid(N / 128, M / 128);
        gemm_bf16_kernel<128,128,4,2,EPI><<<grid, 256, SMEM>>>(
            Ah, Al, Bh, Bl, bias, C, Oh, Ol, M, N, K, lda, ldc);
    } else {
        constexpr int SMEM = 2 * (2*64 + 2*32) * 40 * 2;
        cudaFuncSetAttribute(gemm_bf16_kernel<64,32,4,2,EPI>,
                             cudaFuncAttributeMaxDynamicSharedMemorySize, SMEM);
        dim3 grid(N / 32, M / 64);
        gemm_bf16_kernel<64,32,4,2,EPI><<<grid, 256, SMEM>>>(
            Ah, Al, Bh, Bl, bias, C, Oh, Ol, M, N, K, lda, ldc);
    }
}

#define SYM(p, s) cudaGetSymbolAddress((void**)&p, s)

extern "C" void kernel_launch(void* const* d_in, const int* in_sizes, int n_in,
                              void* d_out, int out_size)
{
    const float* x       = (const float*)d_in[0];
    const float* Wq_down = (const float*)d_in[1];
    const float* Wq_up   = (const float*)d_in[2];
    const float* Wq_rope = (const float*)d_in[3];
    const float* Wkv_down= (const float*)d_in[4];
    const float* Wk_up   = (const float*)d_in[5];
    const float* Wk_rope = (const float*)d_in[6];
    const float* Wv_up   = (const float*)d_in[7];
    const float* Wo      = (const float*)d_in[8];
    const float* bo      = (const float*)d_in[9];
    float* out = (float*)d_out;

    float *qcqr, *kc, *kr, *tab;
    SYM(qcqr, g_qcqr); SYM(kc, g_kc); SYM(kr, g_kr); SYM(tab, g_rope);
    bf16 *xh,*xl,*lath,*latl,*qh,*ql,*kh,*kl,*vth,*vtl,*cxh,*cxl;
    SYM(xh, g_xh); SYM(xl, g_xl); SYM(lath, g_lath); SYM(latl, g_latl);
    SYM(qh, g_qh); SYM(ql, g_ql); SYM(kh, g_kh); SYM(kl, g_kl);
    SYM(vth, g_vth); SYM(vtl, g_vtl); SYM(cxh, g_cxh); SYM(cxl, g_cxl);
    bf16 *wdh,*wdl,*wquph,*wqupl,*wkuh,*wkul,*wkrh,*wkrl,*wvuh,*wvul,*woh,*wol;
    SYM(wdh, g_wdh); SYM(wdl, g_wdl); SYM(wquph, g_wquph); SYM(wqupl, g_wqupl);
    SYM(wkuh, g_wkuh); SYM(wkul, g_wkul); SYM(wkrh, g_wkrh); SYM(wkrl, g_wkrl);
    SYM(wvuh, g_wvuh); SYM(wvul, g_wvul); SYM(woh, g_woh); SYM(wol, g_wol);

    // 1: x split
    split_kernel<<<(MM*HID/4 + 255)/256, 256>>>(x, xh, xl, MM*HID);
    // 2: all 8 weight splits in one launch
    {
        WJobs jb;
        const float* srcs[NSEG] = {Wq_down, Wkv_down, Wq_up, Wq_rope,
                                   Wk_up, Wk_rope, Wv_up, Wo};
        bf16* ohs[NSEG] = {wdh, wdh + LAT*HID, wquph, wquph + CC*NH*LAT,
                           wkuh, wkrh, wvuh, woh};
        bf16* ols[NSEG] = {wdl, wdl + LAT*HID, wqupl, wqupl + CC*NH*LAT,
                           wkul, wkrl, wvul, wol};
        long sizes[NSEG] = {(long)LAT*HID, (long)LAT*HID, (long)CC*NH*LAT,
                            (long)RR*NH*LAT, (long)CC*NH*LAT, (long)RR*HID,
                            (long)HID*LAT, (long)HID*HID};
        long cum = 0;
        for (int s = 0; s < NSEG; s++) {
            jb.src[s] = srcs[s]; jb.oh[s] = ohs[s]; jb.ol[s] = ols[s];
            jb.cum[s] = cum; cum += sizes[s];
        }
        jb.cum[NSEG] = cum;
        split_w_kernel<<<(int)((cum/4 + 255)/256), 256>>>(jb);
    }
    // 3: rope table
    rope_table_kernel<<<(SS*16 + 255)/256, 256>>>(tab);
    // 4: fused down-projection (profiled by ncu -s 5)
    run_gemm<1>(xh, xl, wdh, wdl, nullptr, nullptr, lath, latl, MM, 1024, HID, HID, 1024);

    run_gemm<0>(xh, xl, wkrh, wkrl, nullptr, kr, nullptr, nullptr, MM, RR, HID, HID, RR);
    run_gemm<0>(lath, latl, wquph, wqupl, nullptr, qcqr, nullptr, nullptr, MM, 2048, LAT, 1024, 2048);
    run_gemm<0>(lath + 512, latl + 512, wkuh, wkul, nullptr, kc, nullptr, nullptr, MM, CC*NH, LAT, 1024, CC*NH);
    run_gemm<2>(lath + 512, latl + 512, wvuh, wvul, nullptr, nullptr, vth, vtl, MM, HID, LAT, 1024, 0);

    {
        int blocks = (MM*HID/2 + 255) / 256;
        assemble_q_kernel<<<blocks, 256>>>(qcqr, tab, qh, ql);
        assemble_k_kernel<<<blocks, 256>>>(kc, kr, tab, kh, kl);
    }

    {
        size_t smem = (size_t)(4*64*QST + 2*128*VST) * sizeof(bf16);
        cudaFuncSetAttribute(flash_mma_kernel,
                             cudaFuncAttributeMaxDynamicSharedMemorySize, (int)smem);
        dim3 grid(SS / 64, NH, BB);
        flash_mma_kernel<<<grid, 128, smem>>>(qh, ql, kh, kl, vth, vtl, cxh, cxl);
    }

    run_gemm<0>(cxh, cxl, woh, wol, bo, out, nullptr, nullptr, MM, HID, HID, HID, HID);
}

// round 17
// speedup vs baseline: 1.6533x; 1.0314x over previous
#include <cuda_runtime.h>
#include <cuda_bf16.h>
#include <math.h>
#include <stdint.h>

// Problem constants
#define HID 2048
#define NH  16
#define LAT 512
#define RR  32
#define DH  128
#define CC  96
#define BB  2
#define SS  2048
#define MM  (BB*SS)   // 4096

typedef __nv_bfloat16 bf16;

// ---------------- helpers ----------------
__device__ __forceinline__ void mma16816(float* c, const uint32_t* a, const uint32_t* b) {
    asm volatile(
        "mma.sync.aligned.m16n8k16.row.col.f32.bf16.bf16.f32 "
        "{%0,%1,%2,%3}, {%4,%5,%6,%7}, {%8,%9}, {%0,%1,%2,%3};"
        : "+f"(c[0]), "+f"(c[1]), "+f"(c[2]), "+f"(c[3])
        : "r"(a[0]), "r"(a[1]), "r"(a[2]), "r"(a[3]), "r"(b[0]), "r"(b[1]));
}
__device__ __forceinline__ void ldsm_x4(uint32_t* r, uint32_t addr) {
    asm volatile("ldmatrix.sync.aligned.m8n8.x4.shared.b16 {%0,%1,%2,%3}, [%4];"
                 : "=r"(r[0]), "=r"(r[1]), "=r"(r[2]), "=r"(r[3]) : "r"(addr));
}
__device__ __forceinline__ void split_bf16(float x, bf16& h, bf16& l) {
    h = __float2bfloat16_rn(x);
    l = __float2bfloat16_rn(x - __bfloat162float(h));
}
__device__ __forceinline__ void store_planes2(bf16* Oh, bf16* Ol, long i, float a, float b) {
    bf16 h0, l0, h1, l1;
    split_bf16(a, h0, l0); split_bf16(b, h1, l1);
    *(__nv_bfloat162*)(Oh + i) = __nv_bfloat162(h0, h1);
    *(__nv_bfloat162*)(Ol + i) = __nv_bfloat162(l0, l1);
}
__device__ __forceinline__ uint32_t pack_bf16(float lo, float hi) {
    __nv_bfloat162 t(__float2bfloat16_rn(lo), __float2bfloat16_rn(hi));
    return *(uint32_t*)&t;
}
__device__ __forceinline__ float bf16f(bf16 x) { return __bfloat162float(x); }
__device__ __forceinline__ uint32_t smem_u32(const void* p) {
    uint32_t a;
    asm("{ .reg .u64 t; cvta.to.shared.u64 t, %1; cvt.u32.u64 %0, t; }" : "=r"(a) : "l"(p));
    return a;
}
__device__ __forceinline__ void cp16(void* dst, const void* src) {
    asm volatile("cp.async.cg.shared.global [%0], [%1], 16;"
                 :: "r"(smem_u32(dst)), "l"(src));
}
#define CP_COMMIT() asm volatile("cp.async.commit_group;" ::: "memory")
#define CP_WAIT0()  asm volatile("cp.async.wait_group 0;" ::: "memory")
#define CP_WAIT1()  asm volatile("cp.async.wait_group 1;" ::: "memory")

// -------- scratch --------
__device__ float g_qcqr[MM*2048];
__device__ float g_kc [MM*(CC*NH)];
__device__ float g_kr [MM*RR];
__device__ float g_rope[SS*16*2];
__device__ bf16 g_xh [MM*HID],  g_xl [MM*HID];
__device__ bf16 g_lath[MM*1024], g_latl[MM*1024];
__device__ bf16 g_qh [MM*HID],  g_ql [MM*HID];
__device__ bf16 g_kh [MM*HID],  g_kl [MM*HID];
__device__ bf16 g_vth[BB*NH*DH*SS], g_vtl[BB*NH*DH*SS];
__device__ bf16 g_cxh[MM*HID],  g_cxl[MM*HID];
__device__ bf16 g_wdh  [1024*HID], g_wdl  [1024*HID];
__device__ bf16 g_wquph[2048*LAT], g_wqupl[2048*LAT];
__device__ bf16 g_wkuh [CC*NH*LAT], g_wkul[CC*NH*LAT];
__device__ bf16 g_wkrh [RR*HID],   g_wkrl [RR*HID];
__device__ bf16 g_wvuh [HID*LAT],  g_wvul [HID*LAT];
__device__ bf16 g_woh  [HID*HID],  g_wol  [HID*HID];

// ==================== splits ====================
__global__ void split_kernel(const float* __restrict__ src,
                             bf16* __restrict__ h, bf16* __restrict__ l, int n)
{
    int i = (blockIdx.x * blockDim.x + threadIdx.x) * 4;
    if (i >= n) return;
    float4 v = *(const float4*)(src + i);
    bf16 hx, lx, hy, ly, hz, lz, hw, lw;
    split_bf16(v.x, hx, lx); split_bf16(v.y, hy, ly);
    split_bf16(v.z, hz, lz); split_bf16(v.w, hw, lw);
    *(__nv_bfloat162*)(h + i)     = __nv_bfloat162(hx, hy);
    *(__nv_bfloat162*)(h + i + 2) = __nv_bfloat162(hz, hw);
    *(__nv_bfloat162*)(l + i)     = __nv_bfloat162(lx, ly);
    *(__nv_bfloat162*)(l + i + 2) = __nv_bfloat162(lz, lw);
}

#define NSEG 8
struct WJobs {
    const float* src[NSEG];
    bf16* oh[NSEG];
    bf16* ol[NSEG];
    long cum[NSEG + 1];
};
__global__ void split_w_kernel(WJobs jb)
{
    long i = ((long)blockIdx.x * blockDim.x + threadIdx.x) * 4;
    if (i >= jb.cum[NSEG]) return;
    int s = 0;
#pragma unroll
    for (int k = 0; k < NSEG - 1; k++) s += (i >= jb.cum[k + 1]) ? 1 : 0;
    long off = i - jb.cum[s];
    float4 v = *(const float4*)(jb.src[s] + off);
    bf16 hx, lx, hy, ly, hz, lz, hw, lw;
    split_bf16(v.x, hx, lx); split_bf16(v.y, hy, ly);
    split_bf16(v.z, hz, lz); split_bf16(v.w, hw, lw);
    *(__nv_bfloat162*)(jb.oh[s] + off)     = __nv_bfloat162(hx, hy);
    *(__nv_bfloat162*)(jb.oh[s] + off + 2) = __nv_bfloat162(hz, hw);
    *(__nv_bfloat162*)(jb.ol[s] + off)     = __nv_bfloat162(lx, ly);
    *(__nv_bfloat162*)(jb.ol[s] + off + 2) = __nv_bfloat162(lz, lw);
}

// ==================== bf16-plane GEMM, cp.async + ldmatrix ====================
// Small 64x64 CTAs (4 warps) for high occupancy (~5 CTAs/SM).
// EPI 0: fp32 out; EPI 1: bf16 planes; EPI 2: bf16 planes V-transposed.
template<int BM, int BN, int WARPS_M, int WARPS_N, int EPI>
__global__ __launch_bounds__(WARPS_M*WARPS_N*32) void gemm_bf16_kernel(
    const bf16* __restrict__ Ah, const bf16* __restrict__ Al,
    const bf16* __restrict__ Bh, const bf16* __restrict__ Bl,
    const float* __restrict__ bias, float* __restrict__ C,
    bf16* __restrict__ Oh, bf16* __restrict__ Ol,
    int M, int N, int K, int lda, int ldc)
{
    constexpr int BK = 32, ST = 40;
    constexpr int THREADS = WARPS_M * WARPS_N * 32;
    constexpr int WTM = BM / WARPS_M;
    constexpr int WTN = BN / WARPS_N;
    constexpr int MT = WTM / 16;
    constexpr int NT = WTN / 8;
    constexpr int SSZ = (2*BM + 2*BN) * ST;

    extern __shared__ bf16 sm[];

    const int bm = blockIdx.y * BM;
    const int bn = blockIdx.x * BN;
    const int tid = threadIdx.x;
    const int wid = tid >> 5;
    const int lane = tid & 31;
    const int wm = wid / WARPS_N;
    const int wn = wid % WARPS_N;
    const int g = lane >> 2;
    const int tig = lane & 3;
    const int lrowA = (lane & 7) + ((lane >> 3) & 1) * 8;
    const int lcolA = (lane >> 4) * 8;
    const int mtx   = lane >> 3;
    const int lrowB = (mtx >> 1) * 8 + (lane & 7);
    const int lcolB = (mtx & 1) * 8;

    const uint32_t sm_u = smem_u32(sm);

    float acc[MT][NT][4];
#pragma unroll
    for (int mt = 0; mt < MT; mt++)
#pragma unroll
        for (int nt = 0; nt < NT; nt++)
#pragma unroll
            for (int i = 0; i < 4; i++) acc[mt][nt][i] = 0.f;

    const int nc = K / BK;

    auto load_stage = [&](int chunk, int s) {
        const long k0 = (long)chunk * BK;
        bf16* stg = sm + s * SSZ;
#pragma unroll
        for (int it = 0; it < (BM*4 + THREADS - 1) / THREADS; it++) {
            int f = tid + it * THREADS;
            if (f < BM*4) {
                int row = f >> 2, cg = f & 3;
                long goff = (long)(bm + row) * lda + k0 + cg * 8;
                cp16(stg + row*ST + cg*8, Ah + goff);
                cp16(stg + BM*ST + row*ST + cg*8, Al + goff);
            }
        }
#pragma unroll
        for (int it = 0; it < (BN*4 + THREADS - 1) / THREADS; it++) {
            int f = tid + it * THREADS;
            if (f < BN*4) {
                int row = f >> 2, cg = f & 3;
                long goff = (long)(bn + row) * K + k0 + cg * 8;
                cp16(stg + 2*BM*ST + row*ST + cg*8, Bh + goff);
                cp16(stg + 2*BM*ST + BN*ST + row*ST + cg*8, Bl + goff);
            }
        }
    };

    load_stage(0, 0);
    CP_COMMIT();

    for (int c = 0; c < nc; c++) {
        const int buf = c & 1;
        if (c + 1 < nc) {
            load_stage(c + 1, buf ^ 1);
            CP_COMMIT();
            CP_WAIT1();
        } else {
            CP_WAIT0();
        }
        __syncthreads();

        const uint32_t uAh = sm_u + (buf * SSZ) * 2;
        const uint32_t uAl = uAh + BM*ST*2;
        const uint32_t uBh = uAh + 2*BM*ST*2;
        const uint32_t uBl = uBh + BN*ST*2;

#pragma unroll
        for (int kk = 0; kk < BK; kk += 16) {
            uint32_t afh[MT][4], afl[MT][4], bfh[NT][2], bfl[NT][2];
#pragma unroll
            for (int mt = 0; mt < MT; mt++) {
                int off = ((wm*WTM + mt*16 + lrowA) * ST + kk + lcolA) * 2;
                ldsm_x4(afh[mt], uAh + off);
                ldsm_x4(afl[mt], uAl + off);
            }
#pragma unroll
            for (int np = 0; np < NT/2; np++) {
                int off = ((wn*WTN + np*16 + lrowB) * ST + kk + lcolB) * 2;
                uint32_t r[4];
                ldsm_x4(r, uBh + off);
                bfh[2*np][0]=r[0]; bfh[2*np][1]=r[1]; bfh[2*np+1][0]=r[2]; bfh[2*np+1][1]=r[3];
                ldsm_x4(r, uBl + off);
                bfl[2*np][0]=r[0]; bfl[2*np][1]=r[1]; bfl[2*np+1][0]=r[2]; bfl[2*np+1][1]=r[3];
            }
#pragma unroll
            for (int mt = 0; mt < MT; mt++)
#pragma unroll
                for (int nt = 0; nt < NT; nt++) {
                    mma16816(acc[mt][nt], afh[mt], bfh[nt]);
                    mma16816(acc[mt][nt], afh[mt], bfl[nt]);
                    mma16816(acc[mt][nt], afl[mt], bfh[nt]);
                }
        }
        __syncthreads();
    }

#pragma unroll
    for (int mt = 0; mt < MT; mt++) {
        int row0 = bm + wm * WTM + mt * 16 + g;
#pragma unroll
        for (int nt = 0; nt < NT; nt++) {
            int colb = bn + wn * WTN + nt * 8 + tig * 2;
            if (EPI == 0) {
                float b0 = bias ? bias[colb] : 0.f;
                float b1 = bias ? bias[colb + 1] : 0.f;
                *(float2*)&C[(long)row0 * ldc + colb] =
                    make_float2(acc[mt][nt][0] + b0, acc[mt][nt][1] + b1);
                *(float2*)&C[(long)(row0 + 8) * ldc + colb] =
                    make_float2(acc[mt][nt][2] + b0, acc[mt][nt][3] + b1);
            } else if (EPI == 1) {
                store_planes2(Oh, Ol, (long)row0 * ldc + colb,
                              acc[mt][nt][0], acc[mt][nt][1]);
                store_planes2(Oh, Ol, (long)(row0 + 8) * ldc + colb,
                              acc[mt][nt][2], acc[mt][nt][3]);
            } else {
                int s = row0 & (SS - 1);
                int bb = row0 >> 11;
                long i0 = ((long)(bb * NH + (colb >> 7)) * DH + (colb & 127)) * SS + s;
                bf16 h, l;
                split_bf16(acc[mt][nt][0], h, l); Oh[i0]      = h; Ol[i0]      = l;
                split_bf16(acc[mt][nt][1], h, l); Oh[i0+SS]   = h; Ol[i0+SS]   = l;
                split_bf16(acc[mt][nt][2], h, l); Oh[i0+8]    = h; Ol[i0+8]    = l;
                split_bf16(acc[mt][nt][3], h, l); Oh[i0+SS+8] = h; Ol[i0+SS+8] = l;
            }
        }
    }
}

// ==================== RoPE table ====================
__global__ void rope_table_kernel(float* __restrict__ tab)
{
    int idx = blockIdx.x * blockDim.x + threadIdx.x;
    if (idx >= SS * 16) return;
    int i = idx & 15;
    int s = idx >> 4;
    float inv = powf(10000.0f, -(float)i / 16.0f);
    float freq = (float)s * inv;
    float cs, sn;
    sincosf(freq, &sn, &cs);
    tab[idx*2+0] = cs;
    tab[idx*2+1] = sn;
}

// ==================== head assembly + RoPE -> bf16 planes ====================
__global__ void assemble_q_kernel(const float* __restrict__ qcqr,
                                  const float* __restrict__ tab,
                                  bf16* __restrict__ qh, bf16* __restrict__ ql)
{
    int p = blockIdx.x * blockDim.x + threadIdx.x;
    if (p >= MM*HID/2) return;
    int idx = p * 2;
    int d = idx & 127;
    int h = (idx >> 7) & 15;
    int t = idx >> 11;
    int s = t & (SS - 1);
    float v0, v1;
    if (d < CC) {
        const float* src = qcqr + (long)t * 2048 + h*CC + d;
        v0 = src[0]; v1 = src[1];
    } else {
        const float* base = qcqr + (long)t * 2048 + 1536 + h*RR;
        int r = d - CC;
#pragma unroll
        for (int j = 0; j < 2; j++) {
            int rr = r + j;
            int i = rr & 15;
            float cs = tab[(s*16+i)*2+0], sn = tab[(s*16+i)*2+1];
            float x = base[rr];
            float xr = (rr < 16) ? -base[rr + 16] : base[rr - 16];
            float v = x * cs + xr * sn;
            if (j == 0) v0 = v; else v1 = v;
        }
    }
    store_planes2(qh, ql, idx, v0, v1);
}

__global__ void assemble_k_kernel(const float* __restrict__ kc,
                                  const float* __restrict__ kr,
                                  const float* __restrict__ tab,
                                  bf16* __restrict__ kh, bf16* __restrict__ kl)
{
    int p = blockIdx.x * blockDim.x + threadIdx.x;
    if (p >= MM*HID/2) return;
    int idx = p * 2;
    int d = idx & 127;
    int h = (idx >> 7) & 15;
    int t = idx >> 11;
    int s = t & (SS - 1);
    float v0, v1;
    if (d < CC) {
        const float* src = kc + (long)t * (CC*NH) + h*CC + d;
        v0 = src[0]; v1 = src[1];
    } else {
        const float* base = kr + (long)t * RR;
        int r = d - CC;
#pragma unroll
        for (int j = 0; j < 2; j++) {
            int rr = r + j;
            int i = rr & 15;
            float cs = tab[(s*16+i)*2+0], sn = tab[(s*16+i)*2+1];
            float x = base[rr];
            float xr = (rr < 16) ? -base[rr + 16] : base[rr - 16];
            float v = x * cs + xr * sn;
            if (j == 0) v0 = v; else v1 = v;
        }
    }
    store_planes2(kh, kl, idx, v0, v1);
}

// ==================== Flash attention (64 q-rows/CTA, round-10 form) ====================
#define QST 136
#define VST 72

__global__ __launch_bounds__(128) void flash_mma_kernel(
    const bf16* __restrict__ Qh_, const bf16* __restrict__ Ql_,
    const bf16* __restrict__ Kh_, const bf16* __restrict__ Kl_,
    const bf16* __restrict__ Vth_, const bf16* __restrict__ Vtl_,
    bf16* __restrict__ Oh, bf16* __restrict__ Ol)
{
    extern __shared__ bf16 smf[];
    bf16* sQh = smf;
    bf16* sQl = sQh + 64*QST;
    bf16* sKh = sQl + 64*QST;
    bf16* sKl = sKh + 64*QST;
    bf16* sVh = sKl + 64*QST;
    bf16* sVl = sVh + 128*VST;

    const int qb = blockIdx.x;
    const int h  = blockIdx.y;
    const int b  = blockIdx.z;
    const int tid = threadIdx.x;
    const int w = tid >> 5;
    const int lane = tid & 31;
    const int g = lane >> 2;
    const int tig = lane & 3;
    const int RS = NH * DH;
    const float scale = 0.08838834764831845f;
    const int lrowA = (lane & 7) + ((lane >> 3) & 1) * 8;
    const int lcolA = (lane >> 4) * 8;
    const int mtx   = lane >> 3;
    const int lrowB = (mtx >> 1) * 8 + (lane & 7);
    const int lcolB = (mtx & 1) * 8;

    const uint32_t uQh = smem_u32(sQh), uQl = smem_u32(sQl);
    const uint32_t uKh = smem_u32(sKh), uKl = smem_u32(sKl);
    const uint32_t uVh = smem_u32(sVh), uVl = smem_u32(sVl);

    {
        const long qoff = ((long)b * SS + qb * 64) * RS + h * DH;
#pragma unroll
        for (int it = 0; it < 8; it++) {
            int f = tid + it * 128;
            int row = f >> 4, ch = (f & 15) * 8;
            cp16(sQh + row*QST + ch, Qh_ + qoff + (long)row * RS + ch);
            cp16(sQl + row*QST + ch, Ql_ + qoff + (long)row * RS + ch);
        }
        CP_COMMIT();
    }

    float m0 = -1e30f, m8 = -1e30f, l0 = 0.f, l8 = 0.f;
    float o[16][4];
#pragma unroll
    for (int nd = 0; nd < 16; nd++)
#pragma unroll
        for (int i = 0; i < 4; i++) o[nd][i] = 0.f;

    for (int kb = 0; kb <= qb; kb++) {
        __syncthreads();
        {
            const long koff = ((long)b * SS + kb * 64) * RS + h * DH;
#pragma unroll
            for (int it = 0; it < 8; it++) {
                int f = tid + it * 128;
                int row = f >> 4, ch = (f & 15) * 8;
                cp16(sKh + row*QST + ch, Kh_ + koff + (long)row * RS + ch);
                cp16(sKl + row*QST + ch, Kl_ + koff + (long)row * RS + ch);
            }
            const long voff = (long)(b * NH + h) * DH * SS + kb * 64;
#pragma unroll
            for (int it = 0; it < 8; it++) {
                int f = tid + it * 128;
                int row = f >> 3, ch = (f & 7) * 8;
                cp16(sVh + row*VST + ch, Vth_ + voff + (long)row * SS + ch);
                cp16(sVl + row*VST + ch, Vtl_ + voff + (long)row * SS + ch);
            }
            CP_COMMIT();
            CP_WAIT0();
        }
        __syncthreads();

        float sc[8][4];
#pragma unroll
        for (int nt = 0; nt < 8; nt++)
#pragma unroll
            for (int i = 0; i < 4; i++) sc[nt][i] = 0.f;

#pragma unroll
        for (int kk = 0; kk < 128; kk += 16) {
            uint32_t ah[4], al[4];
            {
                int off = ((w*16 + lrowA) * QST + kk + lcolA) * 2;
                ldsm_x4(ah, uQh + off);
                ldsm_x4(al, uQl + off);
            }
            uint32_t bh[8][2], bl[8][2];
#pragma unroll
            for (int np = 0; np < 4; np++) {
                int off = ((np*16 + lrowB) * QST + kk + lcolB) * 2;
                uint32_t r[4];
                ldsm_x4(r, uKh + off);
                bh[2*np][0]=r[0]; bh[2*np][1]=r[1]; bh[2*np+1][0]=r[2]; bh[2*np+1][1]=r[3];
                ldsm_x4(r, uKl + off);
                bl[2*np][0]=r[0]; bl[2*np][1]=r[1]; bl[2*np+1][0]=r[2]; bl[2*np+1][1]=r[3];
            }
#pragma unroll
            for (int nt = 0; nt < 8; nt++) {
                mma16816(sc[nt], ah, bh[nt]);
                mma16816(sc[nt], ah, bl[nt]);
                mma16816(sc[nt], al, bh[nt]);
            }
        }

#pragma unroll
        for (int nt = 0; nt < 8; nt++)
#pragma unroll
            for (int i = 0; i < 4; i++) sc[nt][i] *= scale;
        if (kb == qb) {
            int row0 = qb*64 + w*16 + g;
#pragma unroll
            for (int nt = 0; nt < 8; nt++) {
                int col = kb*64 + nt*8 + tig*2;
                if (col     > row0)     sc[nt][0] = -1e30f;
                if (col + 1 > row0)     sc[nt][1] = -1e30f;
                if (col     > row0 + 8) sc[nt][2] = -1e30f;
                if (col + 1 > row0 + 8) sc[nt][3] = -1e30f;
            }
        }

        float r0 = -1e30f, r8 = -1e30f;
#pragma unroll
        for (int nt = 0; nt < 8; nt++) {
            r0 = fmaxf(r0, fmaxf(sc[nt][0], sc[nt][1]));
            r8 = fmaxf(r8, fmaxf(sc[nt][2], sc[nt][3]));
        }
        r0 = fmaxf(r0, __shfl_xor_sync(0xffffffffu, r0, 1));
        r0 = fmaxf(r0, __shfl_xor_sync(0xffffffffu, r0, 2));
        r8 = fmaxf(r8, __shfl_xor_sync(0xffffffffu, r8, 1));
        r8 = fmaxf(r8, __shfl_xor_sync(0xffffffffu, r8, 2));
        float mn0 = fmaxf(m0, r0), mn8 = fmaxf(m8, r8);
        float alpha0 = __expf(m0 - mn0), alpha8 = __expf(m8 - mn8);
        float s0 = 0.f, s8 = 0.f;
#pragma unroll
        for (int nt = 0; nt < 8; nt++) {
            sc[nt][0] = __expf(sc[nt][0] - mn0);
            sc[nt][1] = __expf(sc[nt][1] - mn0);
            sc[nt][2] = __expf(sc[nt][2] - mn8);
            sc[nt][3] = __expf(sc[nt][3] - mn8);
            s0 += sc[nt][0] + sc[nt][1];
            s8 += sc[nt][2] + sc[nt][3];
        }
        s0 += __shfl_xor_sync(0xffffffffu, s0, 1);
        s0 += __shfl_xor_sync(0xffffffffu, s0, 2);
        s8 += __shfl_xor_sync(0xffffffffu, s8, 1);
        s8 += __shfl_xor_sync(0xffffffffu, s8, 2);
        l0 = l0 * alpha0 + s0; l8 = l8 * alpha8 + s8;
        m0 = mn0; m8 = mn8;
#pragma unroll
        for (int nd = 0; nd < 16; nd++) {
            o[nd][0] *= alpha0; o[nd][1] *= alpha0;
            o[nd][2] *= alpha8; o[nd][3] *= alpha8;
        }

#pragma unroll
        for (int t = 0; t < 4; t++) {
            uint32_t ph[4], pl[4];
            {
                float p00 = sc[2*t][0],   p01 = sc[2*t][1];
                float p02 = sc[2*t][2],   p03 = sc[2*t][3];
                float p10 = sc[2*t+1][0], p11 = sc[2*t+1][1];
                float p12 = sc[2*t+1][2], p13 = sc[2*t+1][3];
                ph[0] = pack_bf16(p00, p01);
                ph[1] = pack_bf16(p02, p03);
                ph[2] = pack_bf16(p10, p11);
                ph[3] = pack_bf16(p12, p13);
                __nv_bfloat162 hh;
                hh = *(__nv_bfloat162*)&ph[0];
                pl[0] = pack_bf16(p00 - bf16f(hh.x), p01 - bf16f(hh.y));
                hh = *(__nv_bfloat162*)&ph[1];
                pl[1] = pack_bf16(p02 - bf16f(hh.x), p03 - bf16f(hh.y));
                hh = *(__nv_bfloat162*)&ph[2];
                pl[2] = pack_bf16(p10 - bf16f(hh.x), p11 - bf16f(hh.y));
                hh = *(__nv_bfloat162*)&ph[3];
                pl[3] = pack_bf16(p12 - bf16f(hh.x), p13 - bf16f(hh.y));
            }
#pragma unroll
            for (int np = 0; np < 8; np++) {
                int off = ((np*16 + lrowB) * VST + t*16 + lcolB) * 2;
                uint32_t vh[4], vl[4];
                ldsm_x4(vh, uVh + off);
                ldsm_x4(vl, uVl + off);
                mma16816(o[2*np],   ph, vh);
                mma16816(o[2*np],   ph, vl);
                mma16816(o[2*np],   pl, vh);
                mma16816(o[2*np+1], ph, vh + 2);
                mma16816(o[2*np+1], ph, vl + 2);
                mma16816(o[2*np+1], pl, vh + 2);
            }
        }
    }

    {
        float inv0 = 1.0f / l0, inv8 = 1.0f / l8;
        int row0 = qb*64 + w*16 + g;
        long i0 = ((long)b * SS + row0) * RS + h * DH;
        long i8 = i0 + 8L * RS;
#pragma unroll
        for (int nd = 0; nd < 16; nd++) {
            int col = nd*8 + tig*2;
            store_planes2(Oh, Ol, i0 + col, o[nd][0] * inv0, o[nd][1] * inv0);
            store_planes2(Oh, Ol, i8 + col, o[nd][2] * inv8, o[nd][3] * inv8);
        }
    }
}

// ==================== launchers ====================
template<int EPI>
static void run_gemm(const bf16* Ah, const bf16* Al, const bf16* Bh, const bf16* Bl,
                     const float* bias, float* C, bf16* Oh, bf16* Ol,
                     int M, int N, int K, int lda, int ldc)
{
    if (N % 64 == 0) {
        constexpr int SMEM = 2 * (2*64 + 2*64) * 40 * 2;   // 40960 B
        cudaFuncSetAttribute(gemm_bf16_kernel<64,64,2,2,EPI>,
                             cudaFuncAttributeMaxDynamicSharedMemorySize, SMEM);
        dim3 grid(N / 64, M / 64);
        gemm_bf16_kernel<64,64,2,2,EPI><<<grid, 128, SMEM>>>(
            Ah, Al, Bh, Bl, bias, C, Oh, Ol, M, N, K, lda, ldc);
    } else {
        constexpr int SMEM = 2 * (2*64 + 2*32) * 40 * 2;
        cudaFuncSetAttribute(gemm_bf16_kernel<64,32,2,2,EPI>,
                             cudaFuncAttributeMaxDynamicSharedMemorySize, SMEM);
        dim3 grid(N / 32, M / 64);
        gemm_bf16_kernel<64,32,2,2,EPI><<<grid, 128, SMEM>>>(
            Ah, Al, Bh, Bl, bias, C, Oh, Ol, M, N, K, lda, ldc);
    }
}

#define SYM(p, s) cudaGetSymbolAddress((void**)&p, s)

extern "C" void kernel_launch(void* const* d_in, const int* in_sizes, int n_in,
                              void* d_out, int out_size)
{
    const float* x       = (const float*)d_in[0];
    const float* Wq_down = (const float*)d_in[1];
    const float* Wq_up   = (const float*)d_in[2];
    const float* Wq_rope = (const float*)d_in[3];
    const float* Wkv_down= (const float*)d_in[4];
    const float* Wk_up   = (const float*)d_in[5];
    const float* Wk_rope = (const float*)d_in[6];
    const float* Wv_up   = (const float*)d_in[7];
    const float* Wo      = (const float*)d_in[8];
    const float* bo      = (const float*)d_in[9];
    float* out = (float*)d_out;

    float *qcqr, *kc, *kr, *tab;
    SYM(qcqr, g_qcqr); SYM(kc, g_kc); SYM(kr, g_kr); SYM(tab, g_rope);
    bf16 *xh,*xl,*lath,*latl,*qh,*ql,*kh,*kl,*vth,*vtl,*cxh,*cxl;
    SYM(xh, g_xh); SYM(xl, g_xl); SYM(lath, g_lath); SYM(latl, g_latl);
    SYM(qh, g_qh); SYM(ql, g_ql); SYM(kh, g_kh); SYM(kl, g_kl);
    SYM(vth, g_vth); SYM(vtl, g_vtl); SYM(cxh, g_cxh); SYM(cxl, g_cxl);
    bf16 *wdh,*wdl,*wquph,*wqupl,*wkuh,*wkul,*wkrh,*wkrl,*wvuh,*wvul,*woh,*wol;
    SYM(wdh, g_wdh); SYM(wdl, g_wdl); SYM(wquph, g_wquph); SYM(wqupl, g_wqupl);
    SYM(wkuh, g_wkuh); SYM(wkul, g_wkul); SYM(wkrh, g_wkrh); SYM(wkrl, g_wkrl);
    SYM(wvuh, g_wvuh); SYM(wvul, g_wvul); SYM(woh, g_woh); SYM(wol, g_wol);

    // 1: x split
    split_kernel<<<(MM*HID/4 + 255)/256, 256>>>(x, xh, xl, MM*HID);
    // 2: all 8 weight splits in one launch
    {
        WJobs jb;
        const float* srcs[NSEG] = {Wq_down, Wkv_down, Wq_up, Wq_rope,
                                   Wk_up, Wk_rope, Wv_up, Wo};
        bf16* ohs[NSEG] = {wdh, wdh + LAT*HID, wquph, wquph + CC*NH*LAT,
                           wkuh, wkrh, wvuh, woh};
        bf16* ols[NSEG] = {wdl, wdl + LAT*HID, wqupl, wqupl + CC*NH*LAT,
                           wkul, wkrl, wvul, wol};
        long sizes[NSEG] = {(long)LAT*HID, (long)LAT*HID, (long)CC*NH*LAT,
                            (long)RR*NH*LAT, (long)CC*NH*LAT, (long)RR*HID,
                            (long)HID*LAT, (long)HID*HID};
        long cum = 0;
        for (int s = 0; s < NSEG; s++) {
            jb.src[s] = srcs[s]; jb.oh[s] = ohs[s]; jb.ol[s] = ols[s];
            jb.cum[s] = cum; cum += sizes[s];
        }
        jb.cum[NSEG] = cum;
        split_w_kernel<<<(int)((cum/4 + 255)/256), 256>>>(jb);
    }
    // 3: rope table
    rope_table_kernel<<<(SS*16 + 255)/256, 256>>>(tab);
    // 4: fused down-projection (profiled by ncu -s 5)
    run_gemm<1>(xh, xl, wdh, wdl, nullptr, nullptr, lath, latl, MM, 1024, HID, HID, 1024);

    run_gemm<0>(xh, xl, wkrh, wkrl, nullptr, kr, nullptr, nullptr, MM, RR, HID, HID, RR);
    run_gemm<0>(lath, latl, wquph, wqupl, nullptr, qcqr, nullptr, nullptr, MM, 2048, LAT, 1024, 2048);
    run_gemm<0>(lath + 512, latl + 512, wkuh, wkul, nullptr, kc, nullptr, nullptr, MM, CC*NH, LAT, 1024, CC*NH);
    run_gemm<2>(lath + 512, latl + 512, wvuh, wvul, nullptr, nullptr, vth, vtl, MM, HID, LAT, 1024, 0);

    {
        int blocks = (MM*HID/2 + 255) / 256;
        assemble_q_kernel<<<blocks, 256>>>(qcqr, tab, qh, ql);
        assemble_k_kernel<<<blocks, 256>>>(kc, kr, tab, kh, kl);
    }

    {
        size_t smem = (size_t)(4*64*QST + 2*128*VST) * sizeof(bf16);
        cudaFuncSetAttribute(flash_mma_kernel,
                             cudaFuncAttributeMaxDynamicSharedMemorySize, (int)smem);
        dim3 grid(SS / 64, NH, BB);
        flash_mma_kernel<<<grid, 128, smem>>>(qh, ql, kh, kl, vth, vtl, cxh, cxl);
    }

    run_gemm<0>(cxh, cxl, woh, wol, bo, out, nullptr, nullptr, MM, HID, HID, HID, HID);
}